// round 14
// baseline (speedup 1.0000x reference)
#include <cuda_runtime.h>
#include <cstdint>

// Problem constants
#define B_   16
#define H_   224
#define W_   224
#define C_   64
#define HO_  112
#define WO_  112
#define NPATCH (HO_ * WO_)          // 12544 per image
#define TOTPATCH (B_ * NPATCH)      // 200704
#define KSEL 1254
#define KCAP 1280                   // per-image kept-list capacity (tie slack)
#define NBIN1 4096                  // round-1 bins (bits 20..31)
#define HBLKS 8                     // hist blocks per image

// Scratch (__device__ globals, no allocs). Zero-init at load; g_hist is
// re-zeroed by scatter each replay (stream-ordered before next replay's K2a).
__device__ float    g_scores[TOTPATCH];   // conv outputs
__device__ unsigned g_hist[B_ * NBIN1];   // per-image round-1 histogram
__device__ unsigned g_thr[B_];            // per-image K-th-largest orderable key
__device__ unsigned g_cand[TOTPATCH];     // boundary-bin candidate keys
__device__ int      g_cidx[TOTPATCH];     // boundary-bin candidate indices
__device__ int      g_kidx[B_ * KCAP];    // kept patch index (within image)
__device__ float    g_kval[B_ * KCAP];    // kept gate value
__device__ unsigned g_kcnt[B_];           // kept count per image

__device__ __forceinline__ unsigned float_orderable(float f)
{
    unsigned u = __float_as_uint(f);
    return u ^ ((u & 0x80000000u) ? 0xFFFFFFFFu : 0x80000000u);
}

// ---------------------------------------------------------------------------
// Kernel 1: fused conv + zero-fill (measured-best 59.5us, unchanged). One
// warp per EIGHT horizontally adjacent patches: reads its 8 KB x tile,
// streams 8 KB of zeros into y (scatter overwrites kept patches later).
// ---------------------------------------------------------------------------
__global__ void conv_zero_kernel(const float* __restrict__ x,
                                 const float* __restrict__ wk,
                                 float* __restrict__ y)
{
    const unsigned warp = (blockIdx.x * blockDim.x + threadIdx.x) >> 5;
    const int lane = threadIdx.x & 31;
    const unsigned p0 = warp * 8;               // first patch of this group
    if (p0 >= TOTPATCH) return;

    const int b   = p0 / NPATCH;
    const int rem = p0 % NPATCH;
    const int ho  = rem / WO_;
    const int wo  = rem % WO_;                  // multiple of 8

    const size_t base = (((size_t)b * H_ + 2 * ho) * W_ + 2 * wo) * C_;
    const float4* xr = reinterpret_cast<const float4*>(x + base);
    float4*       yr = reinterpret_cast<float4*>(y + base);
    const float4* wr = reinterpret_cast<const float4*>(wk);
    const int rs = W_ * (C_ / 4);               // row stride in float4

    const float4 w0 = __ldg(&wr[lane]);
    const float4 w1 = __ldg(&wr[32 + lane]);

    float4 a0[8], a1[8];
    #pragma unroll
    for (int j = 0; j < 8; ++j) a0[j] = __ldcs(&xr[32 * j + lane]);
    #pragma unroll
    for (int j = 0; j < 8; ++j) a1[j] = __ldcs(&xr[rs + 32 * j + lane]);

    const float4 z = make_float4(0.f, 0.f, 0.f, 0.f);
    #pragma unroll
    for (int j = 0; j < 8; ++j) __stcs(&yr[32 * j + lane], z);
    #pragma unroll
    for (int j = 0; j < 8; ++j) __stcs(&yr[rs + 32 * j + lane], z);

    float s[8];
    #pragma unroll
    for (int j = 0; j < 8; ++j) {
        s[j] = a0[j].x * w0.x + a0[j].y * w0.y + a0[j].z * w0.z + a0[j].w * w0.w
             + a1[j].x * w1.x + a1[j].y * w1.y + a1[j].z * w1.z + a1[j].w * w1.w;
    }

    #pragma unroll
    for (int j = 0; j < 8; ++j) {
        #pragma unroll
        for (int off = 16; off; off >>= 1)
            s[j] += __shfl_down_sync(0xffffffffu, s[j], off);
    }

    if (lane == 0) {
        *reinterpret_cast<float4*>(&g_scores[p0])     = make_float4(s[0], s[1], s[2], s[3]);
        *reinterpret_cast<float4*>(&g_scores[p0 + 4]) = make_float4(s[4], s[5], s[6], s[7]);
    }
}

// ---------------------------------------------------------------------------
// Kernel 2a: parallel round-1 histogram. 8 blocks per image; each block
// histograms its 1568-patch chunk in a PRIVATE smem histogram (8x less
// hot-bin contention), then merges only nonzero bins into g_hist with
// spread-address global atomics.
// ---------------------------------------------------------------------------
__global__ void hist_kernel()
{
    __shared__ unsigned hist[NBIN1];

    const int img   = blockIdx.x / HBLKS;
    const int chunk = blockIdx.x % HBLKS;
    const int tid   = threadIdx.x;
    const unsigned bdim = blockDim.x;
    const int CHUNK = NPATCH / HBLKS;          // 1568
    const float4* gb4 = reinterpret_cast<const float4*>(
        g_scores + (size_t)img * NPATCH + chunk * CHUNK);

    for (int i = tid; i < NBIN1; i += bdim) hist[i] = 0u;
    __syncthreads();

    const int nf4 = CHUNK / 4;                 // 392 float4
    for (int i = tid; i < nf4; i += bdim) {
        const float4 v = gb4[i];
        atomicAdd(&hist[float_orderable(v.x) >> 20], 1u);
        atomicAdd(&hist[float_orderable(v.y) >> 20], 1u);
        atomicAdd(&hist[float_orderable(v.z) >> 20], 1u);
        atomicAdd(&hist[float_orderable(v.w) >> 20], 1u);
    }
    __syncthreads();

    for (int i = tid; i < NBIN1; i += bdim) {
        const unsigned c = hist[i];
        if (c) atomicAdd(&g_hist[img * NBIN1 + i], c);
    }
}

// ---------------------------------------------------------------------------
// Kernel 2b: threshold + kept-list compaction. One block per image. Round 1
// histogram comes from g_hist; the single remaining full scan (compaction)
// uses float4 loads and ballot-aggregated emission.
// ---------------------------------------------------------------------------

// All 32 lanes of the warp MUST call this (kept=false for inactive work).
__device__ __forceinline__ void emit_kept(int b, unsigned* s_kcnt,
                                          int lane, bool kept, int idx, float val)
{
    const unsigned m = __ballot_sync(0xffffffffu, kept);
    if (kept) {
        const int leader = __ffs(m) - 1;
        unsigned basep = 0;
        if (lane == leader) basep = atomicAdd(s_kcnt, (unsigned)__popc(m));
        basep = __shfl_sync(m, basep, leader);
        const unsigned slot = basep + __popc(m & ((1u << lane) - 1u));
        if (slot < KCAP) {
            g_kidx[b * KCAP + slot] = idx;
            g_kval[b * KCAP + slot] = val;
        }
    }
}

// All 32 lanes MUST call; collects boundary candidates (key + idx).
__device__ __forceinline__ void emit_cand(unsigned* cand, int* cidx,
                                          unsigned* s_cnt, int lane,
                                          bool take, unsigned key, int idx)
{
    const unsigned m = __ballot_sync(0xffffffffu, take);
    if (take) {
        const int leader = __ffs(m) - 1;
        unsigned basep = 0;
        if (lane == leader) basep = atomicAdd(s_cnt, (unsigned)__popc(m));
        basep = __shfl_sync(m, basep, leader);
        const unsigned slot = basep + __popc(m & ((1u << lane) - 1u));
        cand[slot] = key;
        cidx[slot] = idx;
    }
}

__global__ void select_thr_kernel()
{
    __shared__ unsigned hist[NBIN1];
    __shared__ unsigned chunk[128];
    __shared__ unsigned s_prefix, s_kth, s_cnt, s_kcnt;

    const int b    = blockIdx.x;
    const int tid  = threadIdx.x;
    const int lane = tid & 31;
    const unsigned bdim = blockDim.x;
    const float4* gb4 = reinterpret_cast<const float4*>(g_scores + (size_t)b * NPATCH);
    unsigned* cand = g_cand + (size_t)b * NPATCH;
    int*      cidx = g_cidx + (size_t)b * NPATCH;

    if (tid == 0) { s_cnt = 0u; s_kcnt = 0u; }

    // ---- Round 1: read precomputed histogram (bits [20..31]) ----
    for (int i = tid; i < NBIN1; i += bdim) hist[i] = g_hist[b * NBIN1 + i];
    __syncthreads();
    if (tid < 128) {
        unsigned s = 0;
        #pragma unroll 4
        for (int i = 0; i < 32; ++i) s += hist[tid * 32 + i];
        chunk[tid] = s;
    }
    __syncthreads();
    if (tid == 0) {
        unsigned kth = KSEL;
        int c = 127;
        for (; c > 0; --c) { if (kth <= chunk[c]) break; kth -= chunk[c]; }
        const int base = c * 32;
        int d = 31;
        for (; d > 0; --d) { if (kth <= hist[base + d]) break; kth -= hist[base + d]; }
        s_prefix = (unsigned)(base + d) << 20;
        s_kth = kth;
    }
    __syncthreads();
    const unsigned top = s_prefix >> 20;

    // ---- Compaction pass: float4 scan, ballot-aggregated emission ----
    {
        const int nf4 = NPATCH / 4;                        // 3136
        const unsigned nloop = ((nf4 + bdim - 1) / bdim) * bdim;
        for (unsigned i = tid; i < nloop; i += bdim) {
            const bool valid = (i < (unsigned)nf4);
            float4 v = make_float4(0.f, 0.f, 0.f, 0.f);
            if (valid) v = gb4[i];
            const float fe[4] = {v.x, v.y, v.z, v.w};
            #pragma unroll
            for (int j = 0; j < 4; ++j) {
                const float f = fe[j];
                const unsigned u = float_orderable(f);
                const unsigned bin = u >> 20;
                const int idx = (int)(4 * i + j);
                emit_kept(b, &s_kcnt, lane, valid && (bin > top), idx, f);
                emit_cand(cand, cidx, &s_cnt, lane, valid && (bin == top), u, idx);
            }
        }
    }
    __syncthreads();
    const unsigned cnt = s_cnt;

    // ---- Round 2: bits [9..19], 2048 bins over candidates ----
    for (int i = tid; i < 2048; i += bdim) hist[i] = 0u;
    __syncthreads();
    for (unsigned i = tid; i < cnt; i += bdim)
        atomicAdd(&hist[(cand[i] >> 9) & 2047u], 1u);
    __syncthreads();
    if (tid < 64) {
        unsigned s = 0;
        #pragma unroll 4
        for (int i = 0; i < 32; ++i) s += hist[tid * 32 + i];
        chunk[tid] = s;
    }
    __syncthreads();
    if (tid == 0) {
        unsigned kth = s_kth;
        int c = 63;
        for (; c > 0; --c) { if (kth <= chunk[c]) break; kth -= chunk[c]; }
        const int base = c * 32;
        int d = 31;
        for (; d > 0; --d) { if (kth <= hist[base + d]) break; kth -= hist[base + d]; }
        s_prefix |= (unsigned)(base + d) << 9;
        s_kth = kth;
    }
    __syncthreads();
    const unsigned mid = (s_prefix >> 9) & 2047u;

    // ---- Round 3: bits [0..8], 512 bins over matching candidates ----
    for (int i = tid; i < 512; i += bdim) hist[i] = 0u;
    __syncthreads();
    for (unsigned i = tid; i < cnt; i += bdim) {
        unsigned u = cand[i];
        if (((u >> 9) & 2047u) == mid)
            atomicAdd(&hist[u & 511u], 1u);
    }
    __syncthreads();
    if (tid < 16) {
        unsigned s = 0;
        #pragma unroll 4
        for (int i = 0; i < 32; ++i) s += hist[tid * 32 + i];
        chunk[tid] = s;
    }
    __syncthreads();
    if (tid == 0) {
        unsigned kth = s_kth;
        int c = 15;
        for (; c > 0; --c) { if (kth <= chunk[c]) break; kth -= chunk[c]; }
        const int base = c * 32;
        int d = 31;
        for (; d > 0; --d) { if (kth <= hist[base + d]) break; kth -= hist[base + d]; }
        s_prefix |= (unsigned)(base + d);
        g_thr[b] = s_prefix;
    }
    __syncthreads();
    const unsigned thr = s_prefix;

    // ---- Append boundary candidates >= thr (padded loop, warp-safe) ----
    {
        const unsigned nloop = ((cnt + bdim - 1) / bdim) * bdim;
        for (unsigned i = tid; i < nloop; i += bdim) {
            const bool valid = (i < cnt);
            const unsigned u = valid ? cand[i] : 0u;
            const int     id = valid ? cidx[i] : 0;
            const float   fv = __uint_as_float(
                u ^ ((u & 0x80000000u) ? 0x80000000u : 0xFFFFFFFFu));
            emit_kept(b, &s_kcnt, lane, valid && (u >= thr), id, fv);
        }
    }
    __syncthreads();
    if (tid == 0) g_kcnt[b] = (s_kcnt < KCAP) ? s_kcnt : KCAP;
}

// ---------------------------------------------------------------------------
// Kernel 3: scatter kept patches (round-6 measured version, 11.2us): one
// warp per kept slot, 2 rows x 512 B per patch. Also re-zeros g_hist for the
// next graph replay (stream-ordered).
// ---------------------------------------------------------------------------
__global__ void scatter_kernel(const float* __restrict__ x,
                               float* __restrict__ y)
{
    {
        const unsigned t = blockIdx.x * blockDim.x + threadIdx.x;
        if (t < B_ * NBIN1) g_hist[t] = 0u;
    }

    const unsigned w    = (blockIdx.x * blockDim.x + threadIdx.x) >> 5;
    const int lane      = threadIdx.x & 31;
    const unsigned img  = w / KCAP;
    const unsigned slot = w % KCAP;
    if (img >= B_ || slot >= __ldg(&g_kcnt[img])) return;

    const int   p   = g_kidx[img * KCAP + slot];
    const float val = g_kval[img * KCAP + slot];
    const int ho = p / WO_;
    const int wo = p % WO_;

    const size_t base = (((size_t)img * H_ + 2 * ho) * W_ + 2 * wo) * C_;
    const int rs = W_ * (C_ / 4);
    const float4* xr = reinterpret_cast<const float4*>(x + base);
    float4*       yr = reinterpret_cast<float4*>(y + base);

    float4 v0 = __ldg(&xr[lane]);
    float4 v1 = __ldg(&xr[rs + lane]);
    v0.x *= val; v0.y *= val; v0.z *= val; v0.w *= val;
    v1.x *= val; v1.y *= val; v1.z *= val; v1.w *= val;
    __stcs(&yr[lane],      v0);
    __stcs(&yr[rs + lane], v1);
}

// ---------------------------------------------------------------------------
extern "C" void kernel_launch(void* const* d_in, const int* in_sizes, int n_in,
                              void* d_out, int out_size)
{
    const float* x  = (const float*)d_in[0];   // [16,224,224,64] f32
    const float* wk = (const float*)d_in[1];   // [2,2,64,1] f32
    float* y = (float*)d_out;

    // K1: fused conv + zero-fill, one warp per 8 patches
    {
        const int warps = TOTPATCH / 8;                           // 25088
        const int threads = 256;
        const int blocks = (warps * 32 + threads - 1) / threads;  // 3136
        conv_zero_kernel<<<blocks, threads>>>(x, wk, y);
    }
    // K2a: parallel histogram, 8 blocks per image
    hist_kernel<<<B_ * HBLKS, 512>>>();
    // K2b: threshold + kept-list compaction, one block per image
    select_thr_kernel<<<B_, 1024>>>();
    // K3: one warp per kept slot (+ g_hist re-zero for next replay)
    {
        const int warps = B_ * KCAP;                              // 20480
        const int threads = 256;
        const int blocks = warps * 32 / threads;                  // 2560
        scatter_kernel<<<blocks, threads>>>(x, y);
    }
}

// round 15
// speedup vs baseline: 1.0350x; 1.0350x over previous
#include <cuda_runtime.h>
#include <cstdint>

// Problem constants
#define B_   16
#define H_   224
#define W_   224
#define C_   64
#define HO_  112
#define WO_  112
#define NPATCH (HO_ * WO_)          // 12544 per image
#define TOTPATCH (B_ * NPATCH)      // 200704
#define KSEL 1254
#define KCAP 1280                   // per-image kept-list capacity (tie slack)

// Scratch (__device__ globals, no allocs)
__device__ float    g_scores[TOTPATCH];   // conv outputs
__device__ unsigned g_thr[B_];            // per-image K-th-largest orderable key
__device__ unsigned g_cand[TOTPATCH];     // boundary-bin candidate keys
__device__ int      g_cidx[TOTPATCH];     // boundary-bin candidate indices
__device__ int      g_kidx[B_ * KCAP];    // kept patch index (within image)
__device__ float    g_kval[B_ * KCAP];    // kept gate value
__device__ unsigned g_kcnt[B_];           // kept count per image

__device__ __forceinline__ unsigned float_orderable(float f)
{
    unsigned u = __float_as_uint(f);
    return u ^ ((u & 0x80000000u) ? 0xFFFFFFFFu : 0x80000000u);
}

// ---------------------------------------------------------------------------
// Kernel 1: fused conv + zero-fill (measured-best 59.5us, unchanged). One
// warp per EIGHT horizontally adjacent patches: reads its 8 KB x tile,
// streams 8 KB of zeros into y (scatter overwrites kept patches later).
// ---------------------------------------------------------------------------
__global__ void conv_zero_kernel(const float* __restrict__ x,
                                 const float* __restrict__ wk,
                                 float* __restrict__ y)
{
    const unsigned warp = (blockIdx.x * blockDim.x + threadIdx.x) >> 5;
    const int lane = threadIdx.x & 31;
    const unsigned p0 = warp * 8;               // first patch of this group
    if (p0 >= TOTPATCH) return;

    const int b   = p0 / NPATCH;
    const int rem = p0 % NPATCH;
    const int ho  = rem / WO_;
    const int wo  = rem % WO_;                  // multiple of 8

    const size_t base = (((size_t)b * H_ + 2 * ho) * W_ + 2 * wo) * C_;
    const float4* xr = reinterpret_cast<const float4*>(x + base);
    float4*       yr = reinterpret_cast<float4*>(y + base);
    const float4* wr = reinterpret_cast<const float4*>(wk);
    const int rs = W_ * (C_ / 4);               // row stride in float4

    const float4 w0 = __ldg(&wr[lane]);
    const float4 w1 = __ldg(&wr[32 + lane]);

    float4 a0[8], a1[8];
    #pragma unroll
    for (int j = 0; j < 8; ++j) a0[j] = __ldcs(&xr[32 * j + lane]);
    #pragma unroll
    for (int j = 0; j < 8; ++j) a1[j] = __ldcs(&xr[rs + 32 * j + lane]);

    const float4 z = make_float4(0.f, 0.f, 0.f, 0.f);
    #pragma unroll
    for (int j = 0; j < 8; ++j) __stcs(&yr[32 * j + lane], z);
    #pragma unroll
    for (int j = 0; j < 8; ++j) __stcs(&yr[rs + 32 * j + lane], z);

    float s[8];
    #pragma unroll
    for (int j = 0; j < 8; ++j) {
        s[j] = a0[j].x * w0.x + a0[j].y * w0.y + a0[j].z * w0.z + a0[j].w * w0.w
             + a1[j].x * w1.x + a1[j].y * w1.y + a1[j].z * w1.z + a1[j].w * w1.w;
    }

    #pragma unroll
    for (int j = 0; j < 8; ++j) {
        #pragma unroll
        for (int off = 16; off; off >>= 1)
            s[j] += __shfl_down_sync(0xffffffffu, s[j], off);
    }

    if (lane == 0) {
        *reinterpret_cast<float4*>(&g_scores[p0])     = make_float4(s[0], s[1], s[2], s[3]);
        *reinterpret_cast<float4*>(&g_scores[p0 + 4]) = make_float4(s[4], s[5], s[6], s[7]);
    }
}

// ---------------------------------------------------------------------------
// Warp-cooperative slot allocator: every lane passes its item count (0..4);
// returns this lane's exclusive base slot. ALL 32 lanes must participate.
// ---------------------------------------------------------------------------
__device__ __forceinline__ unsigned warp_alloc(unsigned* ctr, int lane, unsigned cnt)
{
    unsigned incl = cnt;
    #pragma unroll
    for (int off = 1; off < 32; off <<= 1) {
        unsigned n = __shfl_up_sync(0xffffffffu, incl, off);
        if (lane >= off) incl += n;
    }
    const unsigned total = __shfl_sync(0xffffffffu, incl, 31);
    unsigned basep = 0;
    if (lane == 31 && total) basep = atomicAdd(ctr, total);
    basep = __shfl_sync(0xffffffffu, basep, 31);
    return basep + incl - cnt;
}

// ---------------------------------------------------------------------------
// Kernel 2: per-image K-th-largest threshold via radix select + kept-list
// compaction (R13 structure: 4096/2048/512 bins). Round-1 scan is float4;
// the compaction pass classifies 4 elements per thread locally, then uses
// ONE warp-scan per category per iteration (vs 8 ballots before).
// ---------------------------------------------------------------------------
__global__ void select_thr_kernel()
{
    __shared__ unsigned hist[4096];
    __shared__ unsigned chunk[128];
    __shared__ unsigned s_prefix, s_kth, s_cnt, s_kcnt;

    const int b    = blockIdx.x;
    const int tid  = threadIdx.x;
    const int lane = tid & 31;
    const unsigned bdim = blockDim.x;
    const float4* gb4 = reinterpret_cast<const float4*>(g_scores + (size_t)b * NPATCH);
    unsigned* cand = g_cand + (size_t)b * NPATCH;
    int*      cidx = g_cidx + (size_t)b * NPATCH;
    const int nf4 = NPATCH / 4;                  // 3136

    if (tid == 0) { s_cnt = 0u; s_kcnt = 0u; }

    // ---- Round 1: full float4 scan, 4096 bins over bits [20..31] ----
    for (int i = tid; i < 4096; i += bdim) hist[i] = 0u;
    __syncthreads();
    for (int i = tid; i < nf4; i += bdim) {
        const float4 v = gb4[i];
        atomicAdd(&hist[float_orderable(v.x) >> 20], 1u);
        atomicAdd(&hist[float_orderable(v.y) >> 20], 1u);
        atomicAdd(&hist[float_orderable(v.z) >> 20], 1u);
        atomicAdd(&hist[float_orderable(v.w) >> 20], 1u);
    }
    __syncthreads();
    if (tid < 128) {
        unsigned s = 0;
        #pragma unroll 4
        for (int i = 0; i < 32; ++i) s += hist[tid * 32 + i];
        chunk[tid] = s;
    }
    __syncthreads();
    if (tid == 0) {
        unsigned kth = KSEL;
        int c = 127;
        for (; c > 0; --c) { if (kth <= chunk[c]) break; kth -= chunk[c]; }
        const int base = c * 32;
        int d = 31;
        for (; d > 0; --d) { if (kth <= hist[base + d]) break; kth -= hist[base + d]; }
        s_prefix = (unsigned)(base + d) << 20;
        s_kth = kth;
    }
    __syncthreads();
    const unsigned top = s_prefix >> 20;

    // ---- Compaction pass: float4 scan, warp-scan slot allocation ----
    {
        const unsigned nloop = (((unsigned)nf4 + bdim - 1) / bdim) * bdim;
        for (unsigned i = tid; i < nloop; i += bdim) {
            const bool valid = (i < (unsigned)nf4);
            float4 v = make_float4(0.f, 0.f, 0.f, 0.f);
            if (valid) v = gb4[i];
            const float fe[4] = {v.x, v.y, v.z, v.w};

            // local classification (0..4 keeps, 0..4 candidates per thread)
            unsigned nk = 0, nc = 0;
            float    kv[4];
            int      ki[4];
            unsigned ck[4];
            int      ci[4];
            if (valid) {
                #pragma unroll
                for (int j = 0; j < 4; ++j) {
                    const unsigned u = float_orderable(fe[j]);
                    const unsigned bin = u >> 20;
                    const int idx = (int)(4 * i + j);
                    if (bin > top)       { kv[nk] = fe[j]; ki[nk] = idx; ++nk; }
                    else if (bin == top) { ck[nc] = u;     ci[nc] = idx; ++nc; }
                }
            }

            // one warp-scan per category (all lanes participate)
            const unsigned kbase = warp_alloc(&s_kcnt, lane, nk);
            for (unsigned t = 0; t < nk; ++t) {
                const unsigned slot = kbase + t;
                if (slot < KCAP) {
                    g_kidx[b * KCAP + slot] = ki[t];
                    g_kval[b * KCAP + slot] = kv[t];
                }
            }
            const unsigned cbase = warp_alloc(&s_cnt, lane, nc);
            for (unsigned t = 0; t < nc; ++t) {
                cand[cbase + t] = ck[t];
                cidx[cbase + t] = ci[t];
            }
        }
    }
    __syncthreads();
    const unsigned cnt = s_cnt;

    // ---- Round 2: bits [9..19], 2048 bins over candidates ----
    for (int i = tid; i < 2048; i += bdim) hist[i] = 0u;
    __syncthreads();
    for (unsigned i = tid; i < cnt; i += bdim)
        atomicAdd(&hist[(cand[i] >> 9) & 2047u], 1u);
    __syncthreads();
    if (tid < 64) {
        unsigned s = 0;
        #pragma unroll 4
        for (int i = 0; i < 32; ++i) s += hist[tid * 32 + i];
        chunk[tid] = s;
    }
    __syncthreads();
    if (tid == 0) {
        unsigned kth = s_kth;
        int c = 63;
        for (; c > 0; --c) { if (kth <= chunk[c]) break; kth -= chunk[c]; }
        const int base = c * 32;
        int d = 31;
        for (; d > 0; --d) { if (kth <= hist[base + d]) break; kth -= hist[base + d]; }
        s_prefix |= (unsigned)(base + d) << 9;
        s_kth = kth;
    }
    __syncthreads();
    const unsigned mid = (s_prefix >> 9) & 2047u;

    // ---- Round 3: bits [0..8], 512 bins over matching candidates ----
    for (int i = tid; i < 512; i += bdim) hist[i] = 0u;
    __syncthreads();
    for (unsigned i = tid; i < cnt; i += bdim) {
        unsigned u = cand[i];
        if (((u >> 9) & 2047u) == mid)
            atomicAdd(&hist[u & 511u], 1u);
    }
    __syncthreads();
    if (tid < 16) {
        unsigned s = 0;
        #pragma unroll 4
        for (int i = 0; i < 32; ++i) s += hist[tid * 32 + i];
        chunk[tid] = s;
    }
    __syncthreads();
    if (tid == 0) {
        unsigned kth = s_kth;
        int c = 15;
        for (; c > 0; --c) { if (kth <= chunk[c]) break; kth -= chunk[c]; }
        const int base = c * 32;
        int d = 31;
        for (; d > 0; --d) { if (kth <= hist[base + d]) break; kth -= hist[base + d]; }
        s_prefix |= (unsigned)(base + d);
        g_thr[b] = s_prefix;
    }
    __syncthreads();
    const unsigned thr = s_prefix;

    // ---- Append boundary candidates >= thr (padded loop, warp-safe) ----
    {
        const unsigned nloop = ((cnt + bdim - 1) / bdim) * bdim;
        for (unsigned i = tid; i < nloop; i += bdim) {
            const bool valid = (i < cnt);
            const unsigned u  = valid ? cand[i] : 0u;
            const bool take   = valid && (u >= thr);
            const unsigned slot = warp_alloc(&s_kcnt, lane, take ? 1u : 0u);
            if (take && slot < KCAP) {
                g_kidx[b * KCAP + slot] = cidx[i];
                g_kval[b * KCAP + slot] = __uint_as_float(
                    u ^ ((u & 0x80000000u) ? 0x80000000u : 0xFFFFFFFFu));
            }
        }
    }
    __syncthreads();
    if (tid == 0) g_kcnt[b] = (s_kcnt < KCAP) ? s_kcnt : KCAP;
}

// ---------------------------------------------------------------------------
// Kernel 3: scatter kept patches (round-6 measured version): one warp per
// kept slot, 2 rows x 512 B per patch.
// ---------------------------------------------------------------------------
__global__ void scatter_kernel(const float* __restrict__ x,
                               float* __restrict__ y)
{
    const unsigned w    = (blockIdx.x * blockDim.x + threadIdx.x) >> 5;
    const int lane      = threadIdx.x & 31;
    const unsigned img  = w / KCAP;
    const unsigned slot = w % KCAP;
    if (img >= B_ || slot >= __ldg(&g_kcnt[img])) return;

    const int   p   = g_kidx[img * KCAP + slot];
    const float val = g_kval[img * KCAP + slot];
    const int ho = p / WO_;
    const int wo = p % WO_;

    const size_t base = (((size_t)img * H_ + 2 * ho) * W_ + 2 * wo) * C_;
    const int rs = W_ * (C_ / 4);
    const float4* xr = reinterpret_cast<const float4*>(x + base);
    float4*       yr = reinterpret_cast<float4*>(y + base);

    float4 v0 = __ldg(&xr[lane]);
    float4 v1 = __ldg(&xr[rs + lane]);
    v0.x *= val; v0.y *= val; v0.z *= val; v0.w *= val;
    v1.x *= val; v1.y *= val; v1.z *= val; v1.w *= val;
    __stcs(&yr[lane],      v0);
    __stcs(&yr[rs + lane], v1);
}

// ---------------------------------------------------------------------------
extern "C" void kernel_launch(void* const* d_in, const int* in_sizes, int n_in,
                              void* d_out, int out_size)
{
    const float* x  = (const float*)d_in[0];   // [16,224,224,64] f32
    const float* wk = (const float*)d_in[1];   // [2,2,64,1] f32
    float* y = (float*)d_out;

    // K1: fused conv + zero-fill, one warp per 8 patches
    {
        const int warps = TOTPATCH / 8;                           // 25088
        const int threads = 256;
        const int blocks = (warps * 32 + threads - 1) / threads;  // 3136
        conv_zero_kernel<<<blocks, threads>>>(x, wk, y);
    }
    // K2: one block per image — threshold + kept-list compaction
    select_thr_kernel<<<B_, 1024>>>();
    // K3: one warp per kept slot
    {
        const int warps = B_ * KCAP;                              // 20480
        const int threads = 256;
        const int blocks = warps * 32 / threads;                  // 2560
        scatter_kernel<<<blocks, threads>>>(x, y);
    }
}